// round 3
// baseline (speedup 1.0000x reference)
#include <cuda_runtime.h>
#include <cuda_bf16.h>
#include <cstdint>

// Problem: GNN message passing (aggregate='add', update=identity)
//   x:          [50000, 64] float32
//   edge_index: [2, 800000] int32 on device (JAX x64 disabled silently
//               downcasts jnp.int64 -> int32; in_sizes[1] = 1,600,000).
//   out[dst] += x[src];  edge_index[0]=dst row, edge_index[1]=src row.
//
// Design:
//   - Zero the poisoned output first.
//   - 16 threads per edge, one float4 each: a 256 B gather and a 256 B
//     vector reduction per edge, fully coalesced within a half-warp.
//   - red.global.add.v4.f32 (no-return reduction): 4x fewer atomic ops
//     than scalar atomicAdd, no return trip.
//   - x (12.8 MB) and out (12.8 MB) are both L2-resident -> expect the
//     kernel to be L2-bandwidth/atomic bound, not HBM bound.
//   - Index guard: if dtype assumption is ever wrong, we produce a clean
//     wrong answer (diagnosable rel_err) instead of an illegal access.

#define PARTS_PER_EDGE 16   // 64 floats / 4 per thread

__global__ void zero_out_kernel(float4* __restrict__ out, int n4) {
    int i = blockIdx.x * blockDim.x + threadIdx.x;
    if (i < n4) out[i] = make_float4(0.f, 0.f, 0.f, 0.f);
}

__global__ void __launch_bounds__(256)
scatter_add_kernel(const float4* __restrict__ x,    // [N, 16] as float4
                   const int* __restrict__ ei,      // [2, E] int32
                   float* __restrict__ out,         // [N, 64]
                   int E, int N)
{
    long long total  = (long long)E * PARTS_PER_EDGE;
    long long stride = (long long)gridDim.x * blockDim.x;
    for (long long tid = (long long)blockIdx.x * blockDim.x + threadIdx.x;
         tid < total; tid += stride) {
        int e    = (int)(tid >> 4);   // edge id (16 threads share one edge)
        int part = (int)(tid & 15);   // which float4 of the 64-float row

        // 16 consecutive lanes read the same two indices -> L1 broadcast
        int dst = __ldg(&ei[e]);        // row 0: destination node
        int src = __ldg(&ei[E + e]);    // row 1: source node

        // Safety net (never taken if dtype assumption holds)
        if ((unsigned)dst >= (unsigned)N || (unsigned)src >= (unsigned)N)
            continue;

        float4 v = __ldg(&x[(long long)src * PARTS_PER_EDGE + part]);

        float* dptr = out + (long long)dst * 64 + part * 4;
        asm volatile(
            "red.global.add.v4.f32 [%0], {%1, %2, %3, %4};"
            :: "l"(dptr), "f"(v.x), "f"(v.y), "f"(v.z), "f"(v.w)
            : "memory");
    }
}

extern "C" void kernel_launch(void* const* d_in, const int* in_sizes, int n_in,
                              void* d_out, int out_size)
{
    const float4* x   = (const float4*)d_in[0];   // [50000, 64] f32
    const int*    ei  = (const int*)d_in[1];      // [2, E] int32
    float*        out = (float*)d_out;

    int E  = in_sizes[1] / 2;    // 800000
    int N  = in_sizes[0] / 64;   // 50000 nodes
    int n4 = out_size / 4;       // float4 count of the output

    // 1) zero the (poisoned) output
    {
        int threads = 256;
        int blocks = (n4 + threads - 1) / threads;
        zero_out_kernel<<<blocks, threads>>>((float4*)out, n4);
    }

    // 2) scatter-add: E*16 logical threads, grid-stride
    {
        long long total = (long long)E * PARTS_PER_EDGE;  // 12.8M
        int threads = 256;
        long long blocks_ll = (total + threads - 1) / threads;
        int blocks = (int)((blocks_ll > 131072LL) ? 131072LL : blocks_ll);
        scatter_add_kernel<<<blocks, threads>>>(x, ei, out, E, N);
    }
}

// round 4
// speedup vs baseline: 1.2500x; 1.2500x over previous
#include <cuda_runtime.h>
#include <cuda_bf16.h>
#include <cstdint>

// MessagePassing: out[dst] += x[src] over E=800K edges, x:[50K,64] f32,
// edge_index:[2,E] int32 (JAX x64-disabled downcast).
//
// R3 finding: scatter version is RED-issue bound (12.8M RED.128 lane-ops
// x 1.29 cyc/lane/SM == 61us exactly). Remove atomics from the payload path:
// build CSR per call (histogram -> scan -> fill), then gather per node with
// plain LDG.128 and one ST.128 per output word. Payload phase becomes
// L2-bandwidth bound (~20us) instead of LSU/RED bound.

#define D4        16        // 64 floats = 16 float4 per node row
#define N_MAX     50176
#define E_MAX     800000
#define SCAN_BLK  256
#define NB_MAX    ((N_MAX + SCAN_BLK - 1) / SCAN_BLK)   // 196 <= 1024

__device__ int g_cnt[N_MAX];       // histogram, then reused as fill cursor
__device__ int g_off[N_MAX + 1];   // CSR offsets
__device__ int g_part[N_MAX];      // block-local exclusive scan
__device__ int g_bsum[1024];       // per-block sums for scan
__device__ int g_src[E_MAX];       // src indices grouped by dst

// ---------------- CSR build ----------------

__global__ void k_zero_cnt(int n) {
    int i = blockIdx.x * blockDim.x + threadIdx.x;
    if (i < n) g_cnt[i] = 0;
}

__global__ void k_hist(const int* __restrict__ ei, int E, int N) {
    int e = blockIdx.x * blockDim.x + threadIdx.x;
    if (e < E) {
        int d = ei[e];
        if ((unsigned)d < (unsigned)N) atomicAdd(&g_cnt[d], 1);
    }
}

// block-local exclusive scan of g_cnt -> g_part, block totals -> g_bsum
__global__ void k_scanA(int n) {
    __shared__ int s[SCAN_BLK];
    int i = blockIdx.x * SCAN_BLK + threadIdx.x;
    int v = (i < n) ? g_cnt[i] : 0;
    s[threadIdx.x] = v;
    __syncthreads();
    #pragma unroll
    for (int ofs = 1; ofs < SCAN_BLK; ofs <<= 1) {
        int t = (threadIdx.x >= ofs) ? s[threadIdx.x - ofs] : 0;
        __syncthreads();
        s[threadIdx.x] += t;
        __syncthreads();
    }
    if (i < n) g_part[i] = s[threadIdx.x] - v;      // exclusive
    if (threadIdx.x == SCAN_BLK - 1) g_bsum[blockIdx.x] = s[SCAN_BLK - 1];
}

// single-block exclusive scan of block sums (nb <= 1024)
__global__ void k_scanB(int nb) {
    __shared__ int s[1024];
    int v = (threadIdx.x < nb) ? g_bsum[threadIdx.x] : 0;
    s[threadIdx.x] = v;
    __syncthreads();
    #pragma unroll
    for (int ofs = 1; ofs < 1024; ofs <<= 1) {
        int t = (threadIdx.x >= ofs) ? s[threadIdx.x - ofs] : 0;
        __syncthreads();
        s[threadIdx.x] += t;
        __syncthreads();
    }
    if (threadIdx.x < nb) g_bsum[threadIdx.x] = s[threadIdx.x] - v;  // exclusive
}

// combine -> g_off; also seed fill cursor (reuse g_cnt)
__global__ void k_scanC(int n, int E) {
    int i = blockIdx.x * SCAN_BLK + threadIdx.x;
    if (i < n) {
        int o = g_part[i] + g_bsum[blockIdx.x];
        g_off[i] = o;
        g_cnt[i] = o;    // cursor for fill
    }
    if (i == 0) g_off[n] = E;
}

__global__ void k_fill(const int* __restrict__ ei, int E, int N) {
    int e = blockIdx.x * blockDim.x + threadIdx.x;
    if (e < E) {
        int d = ei[e];
        if ((unsigned)d < (unsigned)N) {
            int pos = atomicAdd(&g_cnt[d], 1);
            g_src[pos] = ei[E + e];   // row 1 = src
        }
    }
}

// ---------------- gather (payload phase, no atomics) ----------------

__global__ void __launch_bounds__(256)
k_gather(const float4* __restrict__ x, float4* __restrict__ out, int N) {
    int t    = blockIdx.x * blockDim.x + threadIdx.x;
    int node = t >> 4;       // 16 lanes per node
    int lane = t & 15;       // which float4 column
    if (node >= N) return;

    int beg = g_off[node];
    int end = g_off[node + 1];

    float4 a0 = make_float4(0.f, 0.f, 0.f, 0.f);
    float4 a1 = make_float4(0.f, 0.f, 0.f, 0.f);

    int j = beg;
    // 4-wide unroll for MLP (independent index + payload loads in flight)
    for (; j + 4 <= end; j += 4) {
        int s0 = __ldg(&g_src[j + 0]);
        int s1 = __ldg(&g_src[j + 1]);
        int s2 = __ldg(&g_src[j + 2]);
        int s3 = __ldg(&g_src[j + 3]);
        float4 v0 = __ldg(&x[s0 * D4 + lane]);
        float4 v1 = __ldg(&x[s1 * D4 + lane]);
        float4 v2 = __ldg(&x[s2 * D4 + lane]);
        float4 v3 = __ldg(&x[s3 * D4 + lane]);
        a0.x += v0.x; a0.y += v0.y; a0.z += v0.z; a0.w += v0.w;
        a1.x += v1.x; a1.y += v1.y; a1.z += v1.z; a1.w += v1.w;
        a0.x += v2.x; a0.y += v2.y; a0.z += v2.z; a0.w += v2.w;
        a1.x += v3.x; a1.y += v3.y; a1.z += v3.z; a1.w += v3.w;
    }
    for (; j < end; ++j) {
        int s0 = __ldg(&g_src[j]);
        float4 v0 = __ldg(&x[s0 * D4 + lane]);
        a0.x += v0.x; a0.y += v0.y; a0.z += v0.z; a0.w += v0.w;
    }
    a0.x += a1.x; a0.y += a1.y; a0.z += a1.z; a0.w += a1.w;
    out[node * D4 + lane] = a0;   // writes every node -> no zero pass needed
}

// ---------------- fallback (proven R3 path) for unexpected shapes ----------------

__global__ void zero_out_kernel(float4* __restrict__ out, int n4) {
    int i = blockIdx.x * blockDim.x + threadIdx.x;
    if (i < n4) out[i] = make_float4(0.f, 0.f, 0.f, 0.f);
}

__global__ void __launch_bounds__(256)
scatter_add_kernel(const float4* __restrict__ x, const int* __restrict__ ei,
                   float* __restrict__ out, int E, int N) {
    long long total  = (long long)E * D4;
    long long stride = (long long)gridDim.x * blockDim.x;
    for (long long tid = (long long)blockIdx.x * blockDim.x + threadIdx.x;
         tid < total; tid += stride) {
        int e = (int)(tid >> 4), part = (int)(tid & 15);
        int dst = __ldg(&ei[e]);
        int src = __ldg(&ei[E + e]);
        if ((unsigned)dst >= (unsigned)N || (unsigned)src >= (unsigned)N) continue;
        float4 v = __ldg(&x[(long long)src * D4 + part]);
        float* dptr = out + (long long)dst * 64 + part * 4;
        asm volatile("red.global.add.v4.f32 [%0], {%1, %2, %3, %4};"
                     :: "l"(dptr), "f"(v.x), "f"(v.y), "f"(v.z), "f"(v.w)
                     : "memory");
    }
}

extern "C" void kernel_launch(void* const* d_in, const int* in_sizes, int n_in,
                              void* d_out, int out_size)
{
    const float4* x   = (const float4*)d_in[0];
    const int*    ei  = (const int*)d_in[1];
    float*        out = (float*)d_out;

    int E = in_sizes[1] / 2;     // 800000
    int N = in_sizes[0] / 64;    // 50000

    if (N > N_MAX || E > E_MAX) {
        // fallback: atomic scatter (R3 kernel, 61us)
        int n4 = out_size / 4;
        zero_out_kernel<<<(n4 + 255) / 256, 256>>>((float4*)out, n4);
        long long total = (long long)E * D4;
        long long bl = (total + 255) / 256;
        int blocks = (int)((bl > 131072LL) ? 131072LL : bl);
        scatter_add_kernel<<<blocks, 256>>>(x, ei, out, E, N);
        return;
    }

    int nbN = (N + SCAN_BLK - 1) / SCAN_BLK;           // 196
    int nbE = (E + 255) / 256;                         // 3125
    int nbT = ((N * D4) + 255) / 256;                  // gather blocks

    k_zero_cnt<<<nbN, SCAN_BLK>>>(N);
    k_hist    <<<nbE, 256>>>(ei, E, N);
    k_scanA   <<<nbN, SCAN_BLK>>>(N);
    k_scanB   <<<1, 1024>>>(nbN);
    k_scanC   <<<nbN, SCAN_BLK>>>(N, E);
    k_fill    <<<nbE, 256>>>(ei, E, N);
    k_gather  <<<nbT, 256>>>(x, (float4*)out, N);
}